// round 17
// baseline (speedup 1.0000x reference)
#include <cuda_runtime.h>
#include <cuda_fp16.h>
#include <cstdint>

// ---------------- table config ----------------
// G=256 knots, tau_j=(j-1)/253, j=0..255; t in [0,1) -> u=t*253+1, j=floor(u) in [1,253]
#define GKNOTS 256
#define HINV   253.0f

// tprep smem: single 40KB B slot + params
#define OFF_B    0
#define OFF_FW   40960
#define OFF_BF   (OFF_FW + 512)
#define OFF_W1W  (OFF_BF + 512)
#define OFF_W1B  (OFF_W1W + 512)
#define OFF_XW   (OFF_W1B + 512)
#define OFF_XB   (OFF_XW + 512)
#define OFF_UB   (OFF_XB + 512)
#define TP_SMEM  (OFF_UB + 512)

__device__ float g_part[14 * GKNOTS * 128];          // per-step partial tiles
__device__ __align__(16) __half g_T16[GKNOTS * 256]; // final table (128KB)

__device__ __forceinline__ unsigned packh2(float a, float b) {
    __half2 h = __floats2half2_rn(a, b);
    return *reinterpret_cast<unsigned*>(&h);
}
__device__ __forceinline__ float tanh_fast(float x) {
    float r;
    asm("tanh.approx.f32 %0, %1;" : "=f"(r) : "f"(x));
    return r;
}
__device__ __forceinline__ void hmma(float* c, const unsigned* a, unsigned b0, unsigned b1) {
    asm volatile("mma.sync.aligned.m16n8k16.row.col.f32.f16.f16.f32 "
                 "{%0,%1,%2,%3}, {%4,%5,%6,%7}, {%8,%9}, {%0,%1,%2,%3};"
                 : "+f"(c[0]), "+f"(c[1]), "+f"(c[2]), "+f"(c[3])
                 : "r"(a[0]), "r"(a[1]), "r"(a[2]), "r"(a[3]), "r"(b0), "r"(b1));
}
__device__ __forceinline__ void mma8(float* acc, const unsigned* a, const uint4* bq) {
#pragma unroll
    for (int j = 0; j < 4; j++) {
        hmma(acc + (2 * j) * 4,     a, bq[j].x, bq[j].y);
        hmma(acc + (2 * j + 1) * 4, a, bq[j].z, bq[j].w);
    }
}
__device__ __forceinline__ float bsp(float s) {
    float t2 = fabsf(s - 2.0f);
    float r1 = fmaf((0.5f * t2 - 1.0f) * t2, t2, 2.0f / 3.0f);
    float am = fmaxf(2.0f - t2, 0.0f);
    float r2 = am * am * am * (1.0f / 6.0f);
    return t2 < 1.0f ? r1 : r2;
}

// ---------------- tprep: one (knot-block, step) per CTA; self-contained B-image gen ----------------
__global__ void __launch_bounds__(512, 1)
tprep_kernel(const float* __restrict__ fourier_weight,
             const float* __restrict__ base_weight,
             const float* __restrict__ spline_weight,
             const float* __restrict__ freq_theta,
             const float* __restrict__ bias_fourier,
             const float* __restrict__ w1w,
             const float* __restrict__ w1b)
{
    extern __shared__ __align__(16) unsigned char smem[];
    const int tid = threadIdx.x, wid = tid >> 5, lane = tid & 31;
    const int wm = wid >> 1, wn = wid & 1;
    const int step  = blockIdx.y;
    const int knot0 = blockIdx.x * 128;

    float* s_fw  = (float*)(smem + OFF_FW);
    float* s_bf  = (float*)(smem + OFF_BF);
    float* s_w1w = (float*)(smem + OFF_W1W);
    float* s_w1b = (float*)(smem + OFF_W1B);
    float* s_xw  = (float*)(smem + OFF_XW);
    float* s_ub  = (float*)(smem + OFF_UB);
    unsigned* smB = (unsigned*)(smem + OFF_B);

    if (tid < 128) {
        float sp = log1pf(expf(freq_theta[tid]));
        float fw = exp10f(-(9.0f * tid) / 127.0f) * (sp + 1e-6f);
        float wv = w1w[tid], wb = w1b[tid];
        s_fw[tid]  = fw;
        s_bf[tid]  = bias_fourier[tid];
        s_w1w[tid] = wv;
        s_w1b[tid] = wb;
        s_xw[tid]  = 2.5f * wv;
        ((float*)(smem + OFF_XB))[tid] = fmaf(wb, 2.5f, 5.5f);
        s_ub[tid]  = fmaf(wb, 2.5f, 0.5f);
    }

    // ---- generate this step's B fragment image directly in smem ----
    const int words = (step < 8) ? 10240 : ((step == 13) ? 4096 : 8192);
    for (int w = tid; w < words; w += 512) {
        int ks   = w >> 10;
        int c4   = (w >> 7) & 7;
        int ln_  = (w >> 2) & 31;
        int q    = w & 3;
        int nt = 2 * c4 + (q >> 1);
        int n  = nt * 8 + (ln_ >> 2);
        float w0, w1;
        if (step < 8) {
            int kl = (ln_ & 3) * 2 + (q & 1) * 8;
            int d  = 16 * step + kl;
            int s  = ks & 1, kh = ks >> 1;
            const float* p = fourier_weight + ((size_t)(s * 128 + n) * 128 + d) * 5 + kh;
            w0 = __ldg(p); w1 = __ldg(p + 5);
        } else {
            int k0 = 16 * ks + (ln_ & 3) * 2 + (q & 1) * 8;
            if (step == 8) {
                const float* p = base_weight + n * 128 + k0;
                w0 = __ldg(p); w1 = __ldg(p + 1);
            } else if (step == 9) {
                int dl = k0 & 15, m = k0 >> 4;
                const float* p = spline_weight + ((size_t)n * 128 + dl) * 8 + m;
                w0 = __ldg(p); w1 = __ldg(p + 8);
            } else if (step <= 12) {
                int bb = step - 10;
                int mslot = k0 >> 5, dl = k0 & 31;
                int d = 16 + bb * 32 + dl, m = mslot + 2;
                const float* p = spline_weight + ((size_t)n * 128 + d) * 8 + m;
                w0 = __ldg(p); w1 = __ldg(p + 8);
            } else {
                int mslot = k0 >> 4, dl = k0 & 15;
                int d = 112 + dl, m = mslot + 2;
                const float* p = spline_weight + ((size_t)n * 128 + d) * 8 + m;
                w0 = __ldg(p); w1 = __ldg(p + 8);
            }
        }
        smB[w] = packh2(w0, w1);
    }
    __syncthreads();

    const int r0 = 16 * wm + (lane >> 2);
    const int c2 = (lane & 3) * 2;
    const int boff0 = (wn * 128 + lane) * 16;
    const float t0 = ((float)(knot0 + r0)     - 1.0f) * (1.0f / HINV);
    const float t1 = ((float)(knot0 + r0 + 8) - 1.0f) * (1.0f / HINV);

#define LOADB(bq, bp, ksv)                                                                   \
    {                                                                                        \
        (bq)[0] = *(const uint4*)((bp) + (ksv) * 4096 + boff0);                              \
        (bq)[1] = *(const uint4*)((bp) + (ksv) * 4096 + boff0 + 512);                        \
        (bq)[2] = *(const uint4*)((bp) + (ksv) * 4096 + boff0 + 1024);                       \
        (bq)[3] = *(const uint4*)((bp) + (ksv) * 4096 + boff0 + 1536);                       \
    }

    float acc[32];
#pragma unroll
    for (int i = 0; i < 32; i++) acc[i] = 0.0f;
    const unsigned char* bp = smem + OFF_B;

    if (step < 8) {
        const int p = step;
        float t2[8], ck[8], sk[8], cp[8], sp_[8];
        uint4 bb[2][4];
        LOADB(bb[0], bp, 0);
#pragma unroll
        for (int ai = 0; ai < 4; ai++) {
            int d = 16 * p + c2 + (ai & 1) + (ai >> 1) * 8;
            float fw = s_fw[d], bf = s_bf[d];
            __sincosf(fmaf(t0, fw, bf), &sk[2 * ai],     &ck[2 * ai]);
            __sincosf(fmaf(t1, fw, bf), &sk[2 * ai + 1], &ck[2 * ai + 1]);
            t2[2 * ai]     = ck[2 * ai]     + ck[2 * ai];
            t2[2 * ai + 1] = ck[2 * ai + 1] + ck[2 * ai + 1];
            cp[2 * ai] = 1.0f; cp[2 * ai + 1] = 1.0f;
            sp_[2 * ai] = 0.0f; sp_[2 * ai + 1] = 0.0f;
        }
#pragma unroll
        for (int ks = 0; ks < 10; ks++) {
            if (ks + 1 < 10) LOADB(bb[(ks + 1) & 1], bp, ks + 1);
            if (ks >= 2 && (ks & 1) == 0) {
#pragma unroll
                for (int i = 0; i < 8; i++) {
                    float cn = fmaf(t2[i], ck[i], -cp[i]);
                    float sn = fmaf(t2[i], sk[i], -sp_[i]);
                    cp[i] = ck[i]; sp_[i] = sk[i];
                    ck[i] = cn; sk[i] = sn;
                }
            }
            unsigned a[4];
            if (ks & 1) {
                a[0] = packh2(sk[0], sk[2]); a[1] = packh2(sk[1], sk[3]);
                a[2] = packh2(sk[4], sk[6]); a[3] = packh2(sk[5], sk[7]);
            } else {
                a[0] = packh2(ck[0], ck[2]); a[1] = packh2(ck[1], ck[3]);
                a[2] = packh2(ck[4], ck[6]); a[3] = packh2(ck[5], ck[7]);
            }
            mma8(acc, a, bb[ks & 1]);
        }
    } else if (step == 8) {
        uint4 bb[2][4];
        LOADB(bb[0], bp, 0);
#pragma unroll
        for (int ks = 0; ks < 8; ks++) {
            if (ks + 1 < 8) LOADB(bb[(ks + 1) & 1], bp, ks + 1);
            unsigned at[4];
#pragma unroll
            for (int kb = 0; kb < 2; kb++) {
                int d = 16 * ks + 8 * kb + c2;
                float2 wv2 = *(const float2*)&s_w1w[d];
                float2 wb2 = *(const float2*)&s_w1b[d];
                float v00 = tanh_fast(fmaf(t0, wv2.x, wb2.x));
                float v01 = tanh_fast(fmaf(t1, wv2.x, wb2.x));
                float v10 = tanh_fast(fmaf(t0, wv2.y, wb2.y));
                float v11 = tanh_fast(fmaf(t1, wv2.y, wb2.y));
                at[2 * kb]     = packh2(v00, v10);
                at[2 * kb + 1] = packh2(v01, v11);
            }
            mma8(acc, at, bb[ks & 1]);
        }
    } else if (step == 9) {
        uint4 bb[2][4];
        LOADB(bb[0], bp, 0);
        float xiA[4], xiB[4];
#pragma unroll
        for (int kb = 0; kb < 2; kb++) {
            int d = 8 * kb + c2;
            float2 xw2 = *(const float2*)&s_xw[d];
            float2 xb2 = *(const float2*)((float*)(smem + OFF_XB) + d);
            xiA[2 * kb]     = fmaf(t0, xw2.x, xb2.x);
            xiA[2 * kb + 1] = fmaf(t0, xw2.y, xb2.y);
            xiB[2 * kb]     = fmaf(t1, xw2.x, xb2.x);
            xiB[2 * kb + 1] = fmaf(t1, xw2.y, xb2.y);
        }
#pragma unroll
        for (int ks = 0; ks < 8; ks++) {
            if (ks + 1 < 8) LOADB(bb[(ks + 1) & 1], bp, ks + 1);
            const float fks = (float)ks;
            unsigned a0[4];
#pragma unroll
            for (int kb = 0; kb < 2; kb++) {
                a0[2 * kb]     = packh2(bsp(xiA[2 * kb] - fks), bsp(xiA[2 * kb + 1] - fks));
                a0[2 * kb + 1] = packh2(bsp(xiB[2 * kb] - fks), bsp(xiB[2 * kb + 1] - fks));
            }
            mma8(acc, a0, bb[ks & 1]);
        }
    } else {
#define SP_BASES(ai, dval, uB0, uB1, uB2, uB3)                                               \
    {                                                                                        \
        float xw = s_xw[dval], ub = s_ub[dval];                                              \
        float u0 = fmaf(t0, xw, ub);                                                         \
        float u1 = fmaf(t1, xw, ub);                                                         \
        float um = 1.0f - u0, u2 = u0 * u0;                                                  \
        uB0[2*(ai)] = um * um * (um * (1.0f/6.0f));                                          \
        uB3[2*(ai)] = u2 * (u0 * (1.0f/6.0f));                                               \
        uB1[2*(ai)] = fmaf(u2, fmaf(u0, 0.5f, -1.0f), 2.0f/3.0f);                            \
        uB2[2*(ai)] = 1.0f - uB0[2*(ai)] - uB1[2*(ai)] - uB3[2*(ai)];                        \
        um = 1.0f - u1; u2 = u1 * u1;                                                        \
        uB0[2*(ai)+1] = um * um * (um * (1.0f/6.0f));                                        \
        uB3[2*(ai)+1] = u2 * (u1 * (1.0f/6.0f));                                             \
        uB1[2*(ai)+1] = fmaf(u2, fmaf(u1, 0.5f, -1.0f), 2.0f/3.0f);                          \
        uB2[2*(ai)+1] = 1.0f - uB0[2*(ai)+1] - uB1[2*(ai)+1] - uB3[2*(ai)+1];                \
    }
#define SP_MMA2(Barr, bqv)                                                                   \
    {                                                                                        \
        unsigned a[4];                                                                       \
        a[0] = packh2(Barr[0], Barr[2]); a[1] = packh2(Barr[1], Barr[3]);                    \
        a[2] = packh2(Barr[4], Barr[6]); a[3] = packh2(Barr[5], Barr[7]);                    \
        mma8(acc, a, bqv);                                                                   \
    }
        if (step <= 12) {
            const int bbk = step - 10;
#pragma unroll
            for (int par = 0; par < 2; par++) {
                float B0[8], B1[8], B2[8], B3[8];
                uint4 q0[4], q1[4];
                LOADB(q0, bp, par);
#pragma unroll
                for (int ai = 0; ai < 4; ai++) {
                    int d = 16 + bbk * 32 + par * 16 + c2 + (ai & 1) + (ai >> 1) * 8;
                    SP_BASES(ai, d, B0, B1, B2, B3)
                }
                LOADB(q1, bp, 2 + par);
                SP_MMA2(B0, q0)
                LOADB(q0, bp, 4 + par);
                SP_MMA2(B1, q1)
                LOADB(q1, bp, 6 + par);
                SP_MMA2(B2, q0)
                SP_MMA2(B3, q1)
            }
        } else {
            float B0[8], B1[8], B2[8], B3[8];
            uint4 q0[4], q1[4];
            LOADB(q0, bp, 0);
#pragma unroll
            for (int ai = 0; ai < 4; ai++) {
                int d = 112 + c2 + (ai & 1) + (ai >> 1) * 8;
                SP_BASES(ai, d, B0, B1, B2, B3)
            }
            LOADB(q1, bp, 1);
            SP_MMA2(B0, q0)
            LOADB(q0, bp, 2);
            SP_MMA2(B1, q1)
            LOADB(q1, bp, 3);
            SP_MMA2(B2, q0)
            SP_MMA2(B3, q1)
        }
    }

    float* d0 = g_part + ((size_t)step * GKNOTS + knot0 + r0) * 128;
    float* d1 = d0 + 8 * 128;
#pragma unroll
    for (int t = 0; t < 8; t++) {
        int col = wn * 64 + t * 8 + c2;
        *(float2*)&d0[col] = make_float2(acc[4 * t],     acc[4 * t + 1]);
        *(float2*)&d1[col] = make_float2(acc[4 * t + 2], acc[4 * t + 3]);
    }
}

// ---------------- pack: sum partials -> fp16 table (x0.5 concat scale) ----------------
__global__ void pack_kernel()
{
    int idx = blockIdx.x * blockDim.x + threadIdx.x;   // 32768
    int row = idx >> 7, c = idx & 127;
    float sF = 0.0f, sS = 0.0f;
#pragma unroll
    for (int s = 0; s < 8; s++)  sF += g_part[((size_t)s * GKNOTS + row) * 128 + c];
#pragma unroll
    for (int s = 8; s < 14; s++) sS += g_part[((size_t)s * GKNOTS + row) * 128 + c];
    g_T16[row * 256 + c]       = __float2half_rn(0.5f * sF);
    g_T16[row * 256 + 128 + c] = __float2half_rn(0.5f * sS);
}

// ---------------- main: one row per warp, cubic-Lagrange interp + LN ----------------
__global__ void __launch_bounds__(256, 1)
interp_kernel(const float* __restrict__ ts,
              const float* __restrict__ ln_w,
              const float* __restrict__ ln_b,
              const float* __restrict__ scale_w,
              float* __restrict__ out)
{
    const int wid = threadIdx.x >> 5, lane = threadIdx.x & 31;
    const int row = blockIdx.x * 8 + wid;
    const int col = lane * 8;

    // start the dependence chain immediately
    float t = __ldg(&ts[row]);
    float u = fmaf(t, HINV, 1.0f);
    int j = (int)floorf(u);
    j = max(1, min(253, j));
    const uint4* p = (const uint4*)g_T16 + (size_t)(j - 1) * 32 + lane;
    uint4 v0 = __ldg(p);
    uint4 v1 = __ldg(p + 32);
    uint4 v2 = __ldg(p + 64);
    uint4 v3 = __ldg(p + 96);

    // overlap: LN params (independent loads) + weights
    float4 w4a = __ldg((const float4*)&ln_w[col]);
    float4 w4b = __ldg((const float4*)&ln_w[col + 4]);
    float4 b4a = __ldg((const float4*)&ln_b[col]);
    float4 b4b = __ldg((const float4*)&ln_b[col + 4]);
    float4 s4a = __ldg((const float4*)&scale_w[col]);
    float4 s4b = __ldg((const float4*)&scale_w[col + 4]);

    float f = u - (float)j;
    float fm1 = f - 1.0f, fm2 = f - 2.0f, fp1 = f + 1.0f;
    float lw0 = -f * fm1 * fm2 * (1.0f / 6.0f);
    float lw1 = fp1 * fm1 * fm2 * 0.5f;
    float lw2 = -fp1 * f * fm2 * 0.5f;
    float lw3 = fp1 * f * fm1 * (1.0f / 6.0f);

    float acc[8];
#pragma unroll
    for (int h = 0; h < 4; h++) {
        unsigned u0 = (&v0.x)[h], u1 = (&v1.x)[h], u2 = (&v2.x)[h], u3 = (&v3.x)[h];
        float2 x0 = __half22float2(*(__half2*)&u0);
        float2 x1 = __half22float2(*(__half2*)&u1);
        float2 x2 = __half22float2(*(__half2*)&u2);
        float2 x3 = __half22float2(*(__half2*)&u3);
        acc[2 * h]     = fmaf(lw3, x3.x, fmaf(lw2, x2.x, fmaf(lw1, x1.x, lw0 * x0.x)));
        acc[2 * h + 1] = fmaf(lw3, x3.y, fmaf(lw2, x2.y, fmaf(lw1, x1.y, lw0 * x0.y)));
    }

    float sum = 0.0f, sq = 0.0f;
#pragma unroll
    for (int i = 0; i < 8; i++) { sum += acc[i]; sq += acc[i] * acc[i]; }
#pragma unroll
    for (int off = 16; off > 0; off >>= 1) {
        sum += __shfl_xor_sync(0xffffffffu, sum, off);
        sq  += __shfl_xor_sync(0xffffffffu, sq,  off);
    }
    float mu   = sum * (1.0f / 256.0f);
    float rstd = rsqrtf(sq * (1.0f / 256.0f) - mu * mu + 1e-5f);

    float4 oa, ob;
    oa.x = ((acc[0] - mu) * rstd * w4a.x + b4a.x) * s4a.x;
    oa.y = ((acc[1] - mu) * rstd * w4a.y + b4a.y) * s4a.y;
    oa.z = ((acc[2] - mu) * rstd * w4a.z + b4a.z) * s4a.z;
    oa.w = ((acc[3] - mu) * rstd * w4a.w + b4a.w) * s4a.w;
    ob.x = ((acc[4] - mu) * rstd * w4b.x + b4b.x) * s4b.x;
    ob.y = ((acc[5] - mu) * rstd * w4b.y + b4b.y) * s4b.y;
    ob.z = ((acc[6] - mu) * rstd * w4b.z + b4b.z) * s4b.z;
    ob.w = ((acc[7] - mu) * rstd * w4b.w + b4b.w) * s4b.w;
    float* op = out + (size_t)row * 256 + col;
    *(float4*)op       = oa;
    *(float4*)(op + 4) = ob;
}

extern "C" void kernel_launch(void* const* d_in, const int* in_sizes, int n_in,
                              void* d_out, int out_size)
{
    const float* timestamps   = (const float*)d_in[0];
    const float* freq_theta   = (const float*)d_in[1];
    const float* bias_fourier = (const float*)d_in[2];
    const float* fourier_w    = (const float*)d_in[3];
    const float* w1w          = (const float*)d_in[4];
    const float* w1b          = (const float*)d_in[5];
    const float* base_w       = (const float*)d_in[6];
    const float* spline_w     = (const float*)d_in[7];
    const float* scale_w      = (const float*)d_in[8];
    const float* ln_w         = (const float*)d_in[9];
    const float* ln_b         = (const float*)d_in[10];
    float* out = (float*)d_out;

    int nrows = in_sizes[0];   // 16384
    cudaFuncSetAttribute(tprep_kernel, cudaFuncAttributeMaxDynamicSharedMemorySize, TP_SMEM);

    tprep_kernel<<<dim3(GKNOTS / 128, 14), 512, TP_SMEM>>>(
        fourier_w, base_w, spline_w, freq_theta, bias_fourier, w1w, w1b);
    pack_kernel<<<32, 1024>>>();
    interp_kernel<<<nrows / 8, 256>>>(timestamps, ln_w, ln_b, scale_w, out);
}